// round 12
// baseline (speedup 1.0000x reference)
#include <cuda_runtime.h>

// PyramidROIAlign, block-per-ROI (128 threads = 4 warps), warp-per-point
// stride-4 walk with depth-2 software pipeline (ping-pong corner buffers:
// loads for point i+2 issued right after computing point i => ~16 LDG.128
// always in flight per warp). Volatile LDG.128 loads, streaming (.cs) stores.
// Output [B,N,7,7,256] f32.

#define POOLN   49
#define C4V     64
#define PER_ROI (POOLN * C4V)

#define LD4(v, addr)                                                           \
    asm volatile("ld.global.nc.v4.f32 {%0,%1,%2,%3}, [%4];"                    \
        : "=f"((v).x), "=f"((v).y), "=f"((v).z), "=f"((v).w) : "l"(addr))

struct Buf8 { float4 c0, c1, c2, c3, c4, c5, c6, c7; };

__device__ __forceinline__ void issue8(Buf8& b, const float4* __restrict__ fm4,
                                       int4 off, int lane)
{
    const float4* p0 = fm4 + off.x + lane;
    const float4* p1 = fm4 + off.y + lane;
    const float4* p2 = fm4 + off.z + lane;
    const float4* p3 = fm4 + off.w + lane;
    LD4(b.c0, p0);      LD4(b.c1, p1);
    LD4(b.c2, p2);      LD4(b.c3, p3);
    LD4(b.c4, p0 + 32); LD4(b.c5, p1 + 32);
    LD4(b.c6, p2 + 32); LD4(b.c7, p3 + 32);
}

__device__ __forceinline__ float4 bilin4(float4 wt, float4 a, float4 b,
                                         float4 c, float4 d)
{
    float4 o;
    o.x = wt.x * a.x + wt.y * b.x + wt.z * c.x + wt.w * d.x;
    o.y = wt.x * a.y + wt.y * b.y + wt.z * c.y + wt.w * d.y;
    o.z = wt.x * a.z + wt.y * b.z + wt.z * c.z + wt.w * d.z;
    o.w = wt.x * a.w + wt.y * b.w + wt.z * c.w + wt.w * d.w;
    return o;
}

__device__ __forceinline__ void st4cs(float4* addr, float4 v)
{
    asm volatile("st.global.cs.v4.f32 [%0], {%1,%2,%3,%4};"
        :: "l"(addr), "f"(v.x), "f"(v.y), "f"(v.z), "f"(v.w));
}

__device__ __forceinline__ void compute_store(const Buf8& b, float4 wt,
                                              float4* outp)
{
    float4 ol = bilin4(wt, b.c0, b.c1, b.c2, b.c3);
    float4 oh = bilin4(wt, b.c4, b.c5, b.c6, b.c7);
    st4cs(outp,      ol);
    st4cs(outp + 32, oh);
}

__global__ void __launch_bounds__(128, 4) roi_align_kernel(
    const float* __restrict__ boxes,       // [B,N,4]
    const int*   __restrict__ image_shape, // [2]
    const float* __restrict__ p2,
    const float* __restrict__ p3,
    const float* __restrict__ p4,
    const float* __restrict__ p5,
    float*       __restrict__ out,         // [B,N,7,7,256]
    int N)
{
    __shared__ int4   s_off[POOLN];
    __shared__ float4 s_w[POOLN];
    __shared__ int    s_lvl;

    const int roi = blockIdx.x;            // b*N + n
    const int tid = threadIdx.x;
    const int b   = roi / N;

    if (tid < POOLN) {
        const float* bx = boxes + roi * 4;
        float y1 = __ldg(bx + 0), x1 = __ldg(bx + 1);
        float y2 = __ldg(bx + 2), x2 = __ldg(bx + 3);
        float bh = y2 - y1, bw = x2 - x1;

        float img_area = (float)image_shape[0] * (float)image_shape[1];
        float scaled = sqrtf(bh * bw) * sqrtf(img_area) * (1.0f / 224.0f);
        float fl = rintf(log2f(scaled));
        fl = fminf(fmaxf(fl, -2.0f), 1.0f);     // lvl = 4+fl in [2,5]
        int lvl = 4 + (int)fl;
        int H = 256 >> (lvl - 2);
        int W = H;

        int py = tid / 7;
        int px = tid - py * 7;
        float ty = (float)py * (1.0f / 6.0f);
        float tx = (float)px * (1.0f / 6.0f);
        float ys = (y1 + bh * ty) * (float)(H - 1);
        float xs = (x1 + bw * tx) * (float)(W - 1);

        float y0f = floorf(ys);
        float x0f = floorf(xs);
        float wy = ys - y0f;
        float wx = xs - x0f;

        int y0  = min(H - 1, max(0, (int)y0f));
        int x0  = min(W - 1, max(0, (int)x0f));
        int y1i = min(H - 1, y0 + 1);
        int x1i = min(W - 1, x0 + 1);

        int base = b * H * W * C4V;             // float4 units, fits int32
        int r0 = base + y0  * W * C4V;
        int r1 = base + y1i * W * C4V;
        s_off[tid] = make_int4(r0 + x0  * C4V,
                               r0 + x1i * C4V,
                               r1 + x0  * C4V,
                               r1 + x1i * C4V);

        float iwy = 1.0f - wy, iwx = 1.0f - wx;
        s_w[tid] = make_float4(iwy * iwx, iwy * wx, wy * iwx, wy * wx);

        if (tid == 0) s_lvl = lvl;
    }
    __syncthreads();

    const int lvl = s_lvl;
    const float4* __restrict__ fm4 =
        (lvl == 2) ? (const float4*)p2 :
        (lvl == 3) ? (const float4*)p3 :
        (lvl == 4) ? (const float4*)p4 : (const float4*)p5;

    const int lane = tid & 31;
    const int wid  = tid >> 5;             // 0..3
    float4* __restrict__ out4 = (float4*)out + (long long)roi * PER_ROI;

    // This warp's points: wid, wid+4, wid+8, ..., < 49.
    // wid==0 -> 13 points; wid 1..3 -> 12 points. Covers all residues mod 4.
    const int m = (POOLN - 1 - wid) / 4 + 1;

    Buf8 A, B;
    issue8(A, fm4, s_off[wid], lane);
    if (m > 1) issue8(B, fm4, s_off[wid + 4], lane);

    for (int i = 0; i < m; i++) {
        int pt = wid + (i << 2);
        float4 wt = s_w[pt];
        float4* op = out4 + pt * C4V + lane;
        int ptn = pt + 8;                  // point for refill (i+2)
        bool refill = (i + 2) < m;

        if ((i & 1) == 0) {
            compute_store(A, wt, op);
            if (refill) issue8(A, fm4, s_off[ptn], lane);
        } else {
            compute_store(B, wt, op);
            if (refill) issue8(B, fm4, s_off[ptn], lane);
        }
    }
}

extern "C" void kernel_launch(void* const* d_in, const int* in_sizes, int n_in,
                              void* d_out, int out_size)
{
    const float* boxes       = (const float*)d_in[0];
    const int*   image_shape = (const int*)d_in[1];
    const float* p2          = (const float*)d_in[2];
    const float* p3          = (const float*)d_in[3];
    const float* p4          = (const float*)d_in[4];
    const float* p5          = (const float*)d_in[5];
    float*       out         = (float*)d_out;

    int B = in_sizes[2] / (256 * 256 * 256);
    if (B < 1) B = 1;
    int N = in_sizes[0] / (4 * B);

    roi_align_kernel<<<B * N, 128>>>(boxes, image_shape, p2, p3, p4, p5, out, N);
}